// round 1
// baseline (speedup 1.0000x reference)
#include <cuda_runtime.h>
#include <math.h>

#define H_DIM  512
#define NGRID  65536
#define NMESH  10242
#define NEDGE  131072

// ---------------- scratch (device globals: allocation-guard safe) ----------
__device__ float g_h[(size_t)NEDGE * H_DIM];    // hidden activations (reused)
__device__ float g_y[(size_t)NEDGE * H_DIM];    // pre-LayerNorm output (reused)
__device__ float g_agg[(size_t)NMESH * H_DIM];  // segment-sum accumulator

// Virtual concatenated A matrix: segment s covers cols [s*512,(s+1)*512);
// row index is optionally indirected through idx (gather).
struct AView {
    const float* base0; const int* idx0;
    const float* base1; const int* idx1;
    const float* base2; const int* idx2;
};

__device__ __forceinline__ const float* seg_row_ptr(const AView& A, int seg, int r) {
    const float* b; const int* ix;
    if (seg == 0)      { b = A.base0; ix = A.idx0; }
    else if (seg == 1) { b = A.base1; ix = A.idx1; }
    else               { b = A.base2; ix = A.idx2; }
    int ar = ix ? ix[r] : r;
    return b + (size_t)ar * H_DIM;
}

__device__ __forceinline__ float silu(float x) {
    return x / (1.0f + expf(-x));
}

// ---------------- fused GEMM: C = act(A @ W + bias) ------------------------
// Block tile 128x128, K-tile 16, 256 threads, 8x8 per-thread microtile.
// ACT: 0 = identity, 1 = SiLU.
template<int ACT>
__global__ __launch_bounds__(256, 2)
void gemm_act(AView A, const float* __restrict__ W, const float* __restrict__ bias,
              float* __restrict__ C, int M, int K)
{
    __shared__ float As[16][132];   // transposed A tile, +4 pad (keeps float4 align)
    __shared__ float Ws[16][128];

    const int t  = threadIdx.x;
    const int bm = blockIdx.y * 128;
    const int bn = blockIdx.x * 128;

    // A-tile loader mapping: 128 rows x 16 cols, 2 float4 per thread
    const int lr = t >> 1;            // 0..127
    const int lc = (t & 1) * 8;       // 0 or 8
    // W-tile loader mapping: 16 rows x 128 cols, 2 float4 per thread
    const int wr = t >> 4;            // 0..15
    const int wc = (t & 15) * 8;      // 0..120
    // compute mapping
    const int tm = (t >> 4) * 8;      // 0..120
    const int tn = (t & 15) * 8;      // 0..120

    float acc[8][8];
    #pragma unroll
    for (int i = 0; i < 8; i++)
        #pragma unroll
        for (int j = 0; j < 8; j++) acc[i][j] = 0.0f;

    int row = bm + lr;
    if (row >= M) row = M - 1;        // clamp: loads stay valid, stores guarded

    for (int kt = 0; kt < K; kt += 16) {
        const int seg = kt >> 9;       // 512 | 16, so one segment per K-tile
        const int kin = kt & 511;

        const float* ap = seg_row_ptr(A, seg, row) + kin + lc;
        float4 v0 = *(const float4*)(ap);
        float4 v1 = *(const float4*)(ap + 4);

        const float* wp = W + (size_t)(kt + wr) * H_DIM + bn + wc;
        float4 w0 = *(const float4*)(wp);
        float4 w1 = *(const float4*)(wp + 4);

        __syncthreads();   // protect previous iteration's smem reads

        As[lc + 0][lr] = v0.x; As[lc + 1][lr] = v0.y;
        As[lc + 2][lr] = v0.z; As[lc + 3][lr] = v0.w;
        As[lc + 4][lr] = v1.x; As[lc + 5][lr] = v1.y;
        As[lc + 6][lr] = v1.z; As[lc + 7][lr] = v1.w;
        *(float4*)&Ws[wr][wc]     = w0;
        *(float4*)&Ws[wr][wc + 4] = w1;

        __syncthreads();

        #pragma unroll
        for (int k = 0; k < 16; k++) {
            float4 a0 = *(const float4*)&As[k][tm];
            float4 a1 = *(const float4*)&As[k][tm + 4];
            float4 b0 = *(const float4*)&Ws[k][tn];
            float4 b1 = *(const float4*)&Ws[k][tn + 4];
            float a[8] = {a0.x, a0.y, a0.z, a0.w, a1.x, a1.y, a1.z, a1.w};
            float b[8] = {b0.x, b0.y, b0.z, b0.w, b1.x, b1.y, b1.z, b1.w};
            #pragma unroll
            for (int i = 0; i < 8; i++)
                #pragma unroll
                for (int j = 0; j < 8; j++)
                    acc[i][j] = fmaf(a[i], b[j], acc[i][j]);
        }
    }

    float bv[8];
    #pragma unroll
    for (int j = 0; j < 8; j++) bv[j] = bias[bn + tn + j];

    #pragma unroll
    for (int i = 0; i < 8; i++) {
        int r = bm + tm + i;
        if (r >= M) break;
        float4 o0, o1;
        float v[8];
        #pragma unroll
        for (int j = 0; j < 8; j++) {
            float x = acc[i][j] + bv[j];
            v[j] = (ACT == 1) ? silu(x) : x;
        }
        o0.x = v[0]; o0.y = v[1]; o0.z = v[2]; o0.w = v[3];
        o1.x = v[4]; o1.y = v[5]; o1.z = v[6]; o1.w = v[7];
        float* cp = C + (size_t)r * H_DIM + bn + tn;
        *(float4*)(cp)     = o0;
        *(float4*)(cp + 4) = o1;
    }
}

// ---------------- LayerNorm (+residual) epilogues ---------------------------
// One block per row of 512. 256 threads x 2 elements.

__device__ __forceinline__ void row_stats(float v0, float v1, float& mean, float& rstd)
{
    float s = v0 + v1;
    float q = v0 * v0 + v1 * v1;
    #pragma unroll
    for (int o = 16; o > 0; o >>= 1) {
        s += __shfl_xor_sync(0xffffffffu, s, o);
        q += __shfl_xor_sync(0xffffffffu, q, o);
    }
    __shared__ float ss[8], sq[8];
    int w = threadIdx.x >> 5, l = threadIdx.x & 31;
    if (l == 0) { ss[w] = s; sq[w] = q; }
    __syncthreads();
    s = ss[0] + ss[1] + ss[2] + ss[3] + ss[4] + ss[5] + ss[6] + ss[7];
    q = sq[0] + sq[1] + sq[2] + sq[3] + sq[4] + sq[5] + sq[6] + sq[7];
    mean = s * (1.0f / 512.0f);
    float var = q * (1.0f / 512.0f) - mean * mean;
    rstd = rsqrtf(var + 1e-5f);
}

// edge path: out = res + LN(y); fused segment-sum scatter into agg[dst[row]]
__global__ void ln_res_scatter(const float* __restrict__ y, const float* __restrict__ res,
                               const float* __restrict__ g, const float* __restrict__ b,
                               const int* __restrict__ dst, float* __restrict__ agg)
{
    const int row = blockIdx.x;
    const int t = threadIdx.x;
    const float* yr = y + (size_t)row * H_DIM;
    float v0 = yr[t], v1 = yr[t + 256];
    float mean, rstd;
    row_stats(v0, v1, mean, rstd);
    const float* rr = res + (size_t)row * H_DIM;
    float o0 = (v0 - mean) * rstd * g[t]       + b[t]       + rr[t];
    float o1 = (v1 - mean) * rstd * g[t + 256] + b[t + 256] + rr[t + 256];
    float* ag = agg + (size_t)dst[row] * H_DIM;
    atomicAdd(&ag[t],       o0);
    atomicAdd(&ag[t + 256], o1);
}

// node paths: out = res + LN(y)
__global__ void ln_res_out(const float* __restrict__ y, const float* __restrict__ res,
                           const float* __restrict__ g, const float* __restrict__ b,
                           float* __restrict__ out)
{
    const int row = blockIdx.x;
    const int t = threadIdx.x;
    const float* yr = y + (size_t)row * H_DIM;
    float v0 = yr[t], v1 = yr[t + 256];
    float mean, rstd;
    row_stats(v0, v1, mean, rstd);
    const float* rr = res + (size_t)row * H_DIM;
    float* orow = out + (size_t)row * H_DIM;
    orow[t]       = (v0 - mean) * rstd * g[t]       + b[t]       + rr[t];
    orow[t + 256] = (v1 - mean) * rstd * g[t + 256] + b[t + 256] + rr[t + 256];
}

__global__ void zero_kernel(float* __restrict__ p, int n)
{
    int i = blockIdx.x * blockDim.x + threadIdx.x;
    if (i < n) p[i] = 0.0f;
}

// ---------------------------------------------------------------------------
extern "C" void kernel_launch(void* const* d_in, const int* in_sizes, int n_in,
                              void* d_out, int out_size)
{
    const float* grid_f = (const float*)d_in[0];
    const float* mesh_f = (const float*)d_in[1];
    const float* edge_f = (const float*)d_in[2];
    const int*   src    = (const int*)d_in[3];
    const int*   dst    = (const int*)d_in[4];
    const float* We1 = (const float*)d_in[5];  const float* be1 = (const float*)d_in[6];
    const float* We2 = (const float*)d_in[7];  const float* be2 = (const float*)d_in[8];
    const float* ge  = (const float*)d_in[9];  const float* bbe = (const float*)d_in[10];
    const float* Wn1 = (const float*)d_in[11]; const float* bn1 = (const float*)d_in[12];
    const float* Wn2 = (const float*)d_in[13]; const float* bn2 = (const float*)d_in[14];
    const float* gn  = (const float*)d_in[15]; const float* bbn = (const float*)d_in[16];
    const float* Wg1 = (const float*)d_in[17]; const float* bg1 = (const float*)d_in[18];
    const float* Wg2 = (const float*)d_in[19]; const float* bg2 = (const float*)d_in[20];
    const float* gg  = (const float*)d_in[21]; const float* bbg = (const float*)d_in[22];

    float *h, *y, *agg;
    cudaGetSymbolAddress((void**)&h,   g_h);
    cudaGetSymbolAddress((void**)&y,   g_y);
    cudaGetSymbolAddress((void**)&agg, g_agg);

    float* grid_out = (float*)d_out;
    float* mesh_out = (float*)d_out + (size_t)NGRID * H_DIM;

    // zero the segment-sum accumulator
    {
        int n = NMESH * H_DIM;
        zero_kernel<<<(n + 255) / 256, 256>>>(agg, n);
    }

    // --- MeshEdgeBlock: cat([edge, grid[src], mesh[dst]]) -> MLP -> +res -> scatter
    {
        AView Ae = { edge_f, nullptr, grid_f, src, mesh_f, dst };
        gemm_act<1><<<dim3(4, NEDGE / 128), 256>>>(Ae, We1, be1, h, NEDGE, 3 * H_DIM);
        AView Ah = { h, nullptr, nullptr, nullptr, nullptr, nullptr };
        gemm_act<0><<<dim3(4, NEDGE / 128), 256>>>(Ah, We2, be2, y, NEDGE, H_DIM);
        ln_res_scatter<<<NEDGE, 256>>>(y, edge_f, ge, bbe, dst, agg);
    }

    // --- MeshNodeBlock: cat([mesh, agg]) -> MLP -> +res
    {
        AView An = { mesh_f, nullptr, agg, nullptr, nullptr, nullptr };
        int gy = (NMESH + 127) / 128;
        gemm_act<1><<<dim3(4, gy), 256>>>(An, Wn1, bn1, h, NMESH, 2 * H_DIM);
        AView Ah = { h, nullptr, nullptr, nullptr, nullptr, nullptr };
        gemm_act<0><<<dim3(4, gy), 256>>>(Ah, Wn2, bn2, y, NMESH, H_DIM);
        ln_res_out<<<NMESH, 256>>>(y, mesh_f, gn, bbn, mesh_out);
    }

    // --- Grid node MLP + residual
    {
        AView Ag = { grid_f, nullptr, nullptr, nullptr, nullptr, nullptr };
        gemm_act<1><<<dim3(4, NGRID / 128), 256>>>(Ag, Wg1, bg1, h, NGRID, H_DIM);
        AView Ah = { h, nullptr, nullptr, nullptr, nullptr, nullptr };
        gemm_act<0><<<dim3(4, NGRID / 128), 256>>>(Ah, Wg2, bg2, y, NGRID, H_DIM);
        ln_res_out<<<NGRID, 256>>>(y, grid_f, gg, bbg, grid_out);
    }
}

// round 3
// speedup vs baseline: 1.8824x; 1.8824x over previous
#include <cuda_runtime.h>
#include <math.h>
#include <stdint.h>

#define H_DIM  512
#define NGRID  65536
#define NMESH  10242
#define NEDGE  131072

// ---------------- scratch (device globals: allocation-guard safe) ----------
__device__ float g_h[(size_t)NEDGE * H_DIM];    // hidden activations (reused)
__device__ float g_y[(size_t)NEDGE * H_DIM];    // pre-LayerNorm output (reused)
__device__ float g_agg[(size_t)NMESH * H_DIM];  // segment-sum accumulator
__device__ float g_wt[(size_t)512 * 4608];      // transposed weights [N=512, K]

// offsets (floats) inside g_wt
#define OFF_WE1T 0                              // 512 x 1536
#define OFF_WN1T (512*1536)                     // 512 x 1024
#define OFF_WE2T (OFF_WN1T + 512*1024)          // 512 x 512
#define OFF_WN2T (OFF_WE2T + 512*512)
#define OFF_WG1T (OFF_WN2T + 512*512)
#define OFF_WG2T (OFF_WG1T + 512*512)

// Virtual concatenated A matrix: segment s covers cols [s*512,(s+1)*512)
struct AView {
    const float* base0; const int* idx0;
    const float* base1; const int* idx1;
    const float* base2; const int* idx2;
};

__device__ __forceinline__ const float* seg_row_ptr(const AView& A, int seg, int r) {
    const float* b; const int* ix;
    if (seg == 0)      { b = A.base0; ix = A.idx0; }
    else if (seg == 1) { b = A.base1; ix = A.idx1; }
    else               { b = A.base2; ix = A.idx2; }
    int ar = ix ? ix[r] : r;
    return b + (size_t)ar * H_DIM;
}

__device__ __forceinline__ float silu(float x) { return x / (1.0f + expf(-x)); }

__device__ __forceinline__ uint32_t smem_u32(const void* p) {
    uint32_t a;
    asm("{ .reg .u64 t; cvta.to.shared.u64 t, %1; cvt.u32.u64 %0, t; }" : "=r"(a) : "l"(p));
    return a;
}
__device__ __forceinline__ void cpasync16(uint32_t s, const void* g) {
    asm volatile("cp.async.cg.shared.global [%0], [%1], 16;" :: "r"(s), "l"(g));
}
__device__ __forceinline__ void mma_tf32(float* d, const uint32_t* a, const uint32_t* b) {
    asm volatile(
        "mma.sync.aligned.m16n8k8.row.col.f32.tf32.tf32.f32 "
        "{%0,%1,%2,%3}, {%4,%5,%6,%7}, {%8,%9}, {%0,%1,%2,%3};"
        : "+f"(d[0]), "+f"(d[1]), "+f"(d[2]), "+f"(d[3])
        : "r"(a[0]), "r"(a[1]), "r"(a[2]), "r"(a[3]), "r"(b[0]), "r"(b[1]));
}

// ---------------- tensor-core GEMM: C = act(A @ Wt^T + bias) ----------------
// BM=BN=128, BK=32. 256 threads = 8 warps in 2(m) x 4(n). Warp tile 64x32.
// Smem rows stride 36 floats: fragment lds bank = 4*g + tc  -> conflict-free.
#define BM 128
#define BN 128
#define BK 32
#define SSTRIDE 36
#define TILE_FLOATS (128 * SSTRIDE)
#define SMEM_BYTES (4 * TILE_FLOATS * 4 * 2)   // A+B, double buffered

template<int ACT>
__global__ __launch_bounds__(256, 2)
void tc_gemm(AView A, const float* __restrict__ Wt, const float* __restrict__ bias,
             float* __restrict__ C, int M, int K)
{
    extern __shared__ float smem[];
    float* As[2] = { smem,                  smem + TILE_FLOATS };
    float* Ws[2] = { smem + 2 * TILE_FLOATS, smem + 3 * TILE_FLOATS };

    const int tid = threadIdx.x, wid = tid >> 5, lane = tid & 31;
    const int g = lane >> 2, tc = lane & 3;          // mma fragment coords
    const int wm = wid & 1, wn = wid >> 1;           // warp grid 2x4
    const int row0 = wm * 64, col0 = wn * 32;
    const int bm = blockIdx.y * BM, bn = blockIdx.x * BN;

    // ---- loader mapping: thread t covers row (t>>1), 16 cols at (t&1)*16
    const int lrow = tid >> 1;
    const int lcol = (tid & 1) * 16;
    int arow = bm + lrow; if (arow >= M) arow = M - 1;
    const float* rpa[3];
    rpa[0] = seg_row_ptr(A, 0, arow);
    rpa[1] = (K > 512)  ? seg_row_ptr(A, 1, arow) : rpa[0];
    rpa[2] = (K > 1024) ? seg_row_ptr(A, 2, arow) : rpa[0];
    const float* bprow = Wt + (size_t)(bn + lrow) * K;

    uint32_t asU[2], wsU[2];
    #pragma unroll
    for (int i = 0; i < 2; i++) {
        asU[i] = smem_u32(As[i]) + (uint32_t)(lrow * SSTRIDE + lcol) * 4;
        wsU[i] = smem_u32(Ws[i]) + (uint32_t)(lrow * SSTRIDE + lcol) * 4;
    }

    auto load_tile = [&](int kt, int buf) {
        const int seg = kt >> 9, kin = kt & 511;
        const float* ap = rpa[seg] + kin + lcol;
        #pragma unroll
        for (int j = 0; j < 4; j++) cpasync16(asU[buf] + j * 16, ap + j * 4);
        const float* bp = bprow + kt + lcol;
        #pragma unroll
        for (int j = 0; j < 4; j++) cpasync16(wsU[buf] + j * 16, bp + j * 4);
        asm volatile("cp.async.commit_group;");
    };

    float acc[4][4][4];
    #pragma unroll
    for (int i = 0; i < 4; i++)
        #pragma unroll
        for (int j = 0; j < 4; j++)
            #pragma unroll
            for (int e = 0; e < 4; e++) acc[i][j][e] = 0.0f;

    const int T = K >> 5;
    load_tile(0, 0);

    for (int t = 0; t < T; ++t) {
        const int cur = t & 1;
        asm volatile("cp.async.wait_group 0;");
        __syncthreads();
        if (t + 1 < T) load_tile((t + 1) << 5, cur ^ 1);

        const float* as = As[cur];
        const float* ws = Ws[cur];
        #pragma unroll
        for (int kk = 0; kk < 4; kk++) {
            const int k = kk * 8;
            uint32_t af[4][4], bf[4][2];
            #pragma unroll
            for (int mt = 0; mt < 4; mt++) {
                const int r = row0 + mt * 16 + g;
                af[mt][0] = __float_as_uint(as[(r)     * SSTRIDE + k + tc]);
                af[mt][1] = __float_as_uint(as[(r + 8) * SSTRIDE + k + tc]);
                af[mt][2] = __float_as_uint(as[(r)     * SSTRIDE + k + tc + 4]);
                af[mt][3] = __float_as_uint(as[(r + 8) * SSTRIDE + k + tc + 4]);
            }
            #pragma unroll
            for (int nt = 0; nt < 4; nt++) {
                const int n = col0 + nt * 8 + g;
                bf[nt][0] = __float_as_uint(ws[n * SSTRIDE + k + tc]);
                bf[nt][1] = __float_as_uint(ws[n * SSTRIDE + k + tc + 4]);
            }
            #pragma unroll
            for (int mt = 0; mt < 4; mt++)
                #pragma unroll
                for (int nt = 0; nt < 4; nt++)
                    mma_tf32(acc[mt][nt], af[mt], bf[nt]);
        }
        __syncthreads();
    }

    // ---- epilogue: bias + activation, direct global stores
    #pragma unroll
    for (int mt = 0; mt < 4; mt++) {
        const int r0 = bm + row0 + mt * 16 + g;
        #pragma unroll
        for (int half = 0; half < 2; half++) {
            const int r = r0 + half * 8;
            if (r >= M) continue;
            float* crow = C + (size_t)r * H_DIM + bn + col0;
            #pragma unroll
            for (int nt = 0; nt < 4; nt++) {
                const int c = nt * 8 + 2 * tc;
                float x0 = acc[mt][nt][half * 2 + 0] + bias[bn + col0 + c];
                float x1 = acc[mt][nt][half * 2 + 1] + bias[bn + col0 + c + 1];
                float2 o;
                o.x = (ACT == 1) ? silu(x0) : x0;
                o.y = (ACT == 1) ? silu(x1) : x1;
                *(float2*)(crow + c) = o;
            }
        }
    }
}

// ---------------- weight transpose: W[K,512] -> Wt[512,K], rounded to tf32 --
__global__ void transpose_w(const float* __restrict__ in, float* __restrict__ out, int K)
{
    __shared__ float t[32][33];
    int k0 = blockIdx.x * 32, n0 = blockIdx.y * 32;
    int x = threadIdx.x, y = threadIdx.y;
    #pragma unroll
    for (int i = 0; i < 32; i += 8) {
        float v = in[(size_t)(k0 + y + i) * 512 + n0 + x];
        uint32_t rb; asm("cvt.rna.tf32.f32 %0, %1;" : "=r"(rb) : "f"(v));
        t[y + i][x] = __uint_as_float(rb);
    }
    __syncthreads();
    #pragma unroll
    for (int i = 0; i < 32; i += 8)
        out[(size_t)(n0 + y + i) * K + k0 + x] = t[x][y + i];
}

// ---------------- LayerNorm (+residual) epilogues ---------------------------
__device__ __forceinline__ void row_stats(float v0, float v1, float& mean, float& rstd)
{
    float s = v0 + v1;
    float q = v0 * v0 + v1 * v1;
    #pragma unroll
    for (int o = 16; o > 0; o >>= 1) {
        s += __shfl_xor_sync(0xffffffffu, s, o);
        q += __shfl_xor_sync(0xffffffffu, q, o);
    }
    __shared__ float ss[8], sq[8];
    int w = threadIdx.x >> 5, l = threadIdx.x & 31;
    if (l == 0) { ss[w] = s; sq[w] = q; }
    __syncthreads();
    s = ss[0] + ss[1] + ss[2] + ss[3] + ss[4] + ss[5] + ss[6] + ss[7];
    q = sq[0] + sq[1] + sq[2] + sq[3] + sq[4] + sq[5] + sq[6] + sq[7];
    mean = s * (1.0f / 512.0f);
    float var = q * (1.0f / 512.0f) - mean * mean;
    rstd = rsqrtf(var + 1e-5f);
}

__global__ void ln_res_scatter(const float* __restrict__ y, const float* __restrict__ res,
                               const float* __restrict__ g, const float* __restrict__ b,
                               const int* __restrict__ dst, float* __restrict__ agg)
{
    const int row = blockIdx.x;
    const int t = threadIdx.x;
    const float* yr = y + (size_t)row * H_DIM;
    float v0 = yr[t], v1 = yr[t + 256];
    float mean, rstd;
    row_stats(v0, v1, mean, rstd);
    const float* rr = res + (size_t)row * H_DIM;
    float o0 = (v0 - mean) * rstd * g[t]       + b[t]       + rr[t];
    float o1 = (v1 - mean) * rstd * g[t + 256] + b[t + 256] + rr[t + 256];
    float* ag = agg + (size_t)dst[row] * H_DIM;
    atomicAdd(&ag[t],       o0);
    atomicAdd(&ag[t + 256], o1);
}

__global__ void ln_res_out(const float* __restrict__ y, const float* __restrict__ res,
                           const float* __restrict__ g, const float* __restrict__ b,
                           float* __restrict__ out)
{
    const int row = blockIdx.x;
    const int t = threadIdx.x;
    const float* yr = y + (size_t)row * H_DIM;
    float v0 = yr[t], v1 = yr[t + 256];
    float mean, rstd;
    row_stats(v0, v1, mean, rstd);
    const float* rr = res + (size_t)row * H_DIM;
    float* orow = out + (size_t)row * H_DIM;
    orow[t]       = (v0 - mean) * rstd * g[t]       + b[t]       + rr[t];
    orow[t + 256] = (v1 - mean) * rstd * g[t + 256] + b[t + 256] + rr[t + 256];
}

__global__ void zero_kernel(float* __restrict__ p, int n)
{
    int i = blockIdx.x * blockDim.x + threadIdx.x;
    if (i < n) p[i] = 0.0f;
}

// ---------------------------------------------------------------------------
extern "C" void kernel_launch(void* const* d_in, const int* in_sizes, int n_in,
                              void* d_out, int out_size)
{
    const float* grid_f = (const float*)d_in[0];
    const float* mesh_f = (const float*)d_in[1];
    const float* edge_f = (const float*)d_in[2];
    const int*   src    = (const int*)d_in[3];
    const int*   dst    = (const int*)d_in[4];
    const float* We1 = (const float*)d_in[5];  const float* be1 = (const float*)d_in[6];
    const float* We2 = (const float*)d_in[7];  const float* be2 = (const float*)d_in[8];
    const float* ge  = (const float*)d_in[9];  const float* bbe = (const float*)d_in[10];
    const float* Wn1 = (const float*)d_in[11]; const float* bn1 = (const float*)d_in[12];
    const float* Wn2 = (const float*)d_in[13]; const float* bn2 = (const float*)d_in[14];
    const float* gn  = (const float*)d_in[15]; const float* bbn = (const float*)d_in[16];
    const float* Wg1 = (const float*)d_in[17]; const float* bg1 = (const float*)d_in[18];
    const float* Wg2 = (const float*)d_in[19]; const float* bg2 = (const float*)d_in[20];
    const float* gg  = (const float*)d_in[21]; const float* bbg = (const float*)d_in[22];

    float *h, *y, *agg, *wt;
    cudaGetSymbolAddress((void**)&h,   g_h);
    cudaGetSymbolAddress((void**)&y,   g_y);
    cudaGetSymbolAddress((void**)&agg, g_agg);
    cudaGetSymbolAddress((void**)&wt,  g_wt);

    cudaFuncSetAttribute(tc_gemm<0>, cudaFuncAttributeMaxDynamicSharedMemorySize, SMEM_BYTES);
    cudaFuncSetAttribute(tc_gemm<1>, cudaFuncAttributeMaxDynamicSharedMemorySize, SMEM_BYTES);

    float* grid_out = (float*)d_out;
    float* mesh_out = (float*)d_out + (size_t)NGRID * H_DIM;

    // weight transposes (+ round-to-nearest tf32)
    dim3 tb(32, 8);
    transpose_w<<<dim3(48, 16), tb>>>(We1, wt + OFF_WE1T, 1536);
    transpose_w<<<dim3(32, 16), tb>>>(Wn1, wt + OFF_WN1T, 1024);
    transpose_w<<<dim3(16, 16), tb>>>(We2, wt + OFF_WE2T, 512);
    transpose_w<<<dim3(16, 16), tb>>>(Wn2, wt + OFF_WN2T, 512);
    transpose_w<<<dim3(16, 16), tb>>>(Wg1, wt + OFF_WG1T, 512);
    transpose_w<<<dim3(16, 16), tb>>>(Wg2, wt + OFF_WG2T, 512);

    { int n = NMESH * H_DIM; zero_kernel<<<(n + 255) / 256, 256>>>(agg, n); }

    // --- MeshEdgeBlock
    {
        AView Ae = { edge_f, nullptr, grid_f, src, mesh_f, dst };
        tc_gemm<1><<<dim3(4, NEDGE / 128), 256, SMEM_BYTES>>>(Ae, wt + OFF_WE1T, be1, h, NEDGE, 1536);
        AView Ah = { h, nullptr, nullptr, nullptr, nullptr, nullptr };
        tc_gemm<0><<<dim3(4, NEDGE / 128), 256, SMEM_BYTES>>>(Ah, wt + OFF_WE2T, be2, y, NEDGE, 512);
        ln_res_scatter<<<NEDGE, 256>>>(y, edge_f, ge, bbe, dst, agg);
    }
    // --- MeshNodeBlock
    {
        AView An = { mesh_f, nullptr, agg, nullptr, nullptr, nullptr };
        int gy = (NMESH + BM - 1) / BM;
        tc_gemm<1><<<dim3(4, gy), 256, SMEM_BYTES>>>(An, wt + OFF_WN1T, bn1, h, NMESH, 1024);
        AView Ah = { h, nullptr, nullptr, nullptr, nullptr, nullptr };
        tc_gemm<0><<<dim3(4, gy), 256, SMEM_BYTES>>>(Ah, wt + OFF_WN2T, bn2, y, NMESH, 512);
        ln_res_out<<<NMESH, 256>>>(y, mesh_f, gn, bbn, mesh_out);
    }
    // --- Grid node MLP
    {
        AView Ag = { grid_f, nullptr, nullptr, nullptr, nullptr, nullptr };
        tc_gemm<1><<<dim3(4, NGRID / 128), 256, SMEM_BYTES>>>(Ag, wt + OFF_WG1T, bg1, h, NGRID, 512);
        AView Ah = { h, nullptr, nullptr, nullptr, nullptr, nullptr };
        tc_gemm<0><<<dim3(4, NGRID / 128), 256, SMEM_BYTES>>>(Ah, wt + OFF_WG2T, bg2, y, NGRID, 512);
        ln_res_out<<<NGRID, 256>>>(y, grid_f, gg, bbg, grid_out);
    }
}

// round 4
// speedup vs baseline: 2.2687x; 1.2052x over previous
#include <cuda_runtime.h>
#include <math.h>
#include <stdint.h>

#define H_DIM  512
#define NGRID  65536
#define NMESH  10242
#define NEDGE  131072

// ---------------- scratch (device globals: allocation-guard safe) ----------
__device__ float g_h[(size_t)NEDGE * H_DIM];
__device__ float g_y[(size_t)NEDGE * H_DIM];
__device__ float g_agg[(size_t)NMESH * H_DIM];
__device__ float g_wt[(size_t)512 * 4608];      // transposed weights [N=512, K]

#define OFF_WE1T 0
#define OFF_WN1T (512*1536)
#define OFF_WE2T (OFF_WN1T + 512*1024)
#define OFF_WN2T (OFF_WE2T + 512*512)
#define OFF_WG1T (OFF_WN2T + 512*512)
#define OFF_WG2T (OFF_WG1T + 512*512)

struct AView {
    const float* base0; const int* idx0;
    const float* base1; const int* idx1;
    const float* base2; const int* idx2;
};

__device__ __forceinline__ const float* seg_row_ptr(const AView& A, int seg, int r) {
    const float* b; const int* ix;
    if (seg == 0)      { b = A.base0; ix = A.idx0; }
    else if (seg == 1) { b = A.base1; ix = A.idx1; }
    else               { b = A.base2; ix = A.idx2; }
    int ar = ix ? ix[r] : r;
    return b + (size_t)ar * H_DIM;
}

__device__ __forceinline__ float silu(float x) { return x / (1.0f + expf(-x)); }

__device__ __forceinline__ uint32_t smem_u32(const void* p) {
    uint32_t a;
    asm("{ .reg .u64 t; cvta.to.shared.u64 t, %1; cvt.u32.u64 %0, t; }" : "=r"(a) : "l"(p));
    return a;
}
__device__ __forceinline__ void cpasync16(uint32_t s, const void* g) {
    asm volatile("cp.async.cg.shared.global [%0], [%1], 16;" :: "r"(s), "l"(g));
}
__device__ __forceinline__ void mma_tf32(float* d, const uint32_t* a, const uint32_t* b) {
    asm volatile(
        "mma.sync.aligned.m16n8k8.row.col.f32.tf32.tf32.f32 "
        "{%0,%1,%2,%3}, {%4,%5,%6,%7}, {%8,%9}, {%0,%1,%2,%3};"
        : "+f"(d[0]), "+f"(d[1]), "+f"(d[2]), "+f"(d[3])
        : "r"(a[0]), "r"(a[1]), "r"(a[2]), "r"(a[3]), "r"(b[0]), "r"(b[1]));
}

// ---------------- tensor-core GEMM: C = act(A @ Wt^T + bias) ----------------
// BM=128, BN=256, BK=32. 256 threads = 8 warps (2m x 4n), warp tile 64x64.
// 3-stage cp.async pipeline. Smem row stride 36 -> conflict-free fragments.
#define BM 128
#define BN 256
#define BK 32
#define SSTRIDE 36
#define ATILE (128 * SSTRIDE)          // floats per A stage
#define BTILE (256 * SSTRIDE)          // floats per B stage
#define STAGE (ATILE + BTILE)
#define NSTG  3
#define SMEM_BYTES (NSTG * STAGE * 4)

template<int ACT>
__global__ __launch_bounds__(256)
void tc_gemm(AView A, const float* __restrict__ Wt, const float* __restrict__ bias,
             float* __restrict__ C, int M, int K)
{
    extern __shared__ float smem[];

    const int tid = threadIdx.x, wid = tid >> 5, lane = tid & 31;
    const int g = lane >> 2, tc = lane & 3;
    const int wm = wid & 1, wn = wid >> 1;           // 2 x 4 warp grid
    const int row0 = wm * 64, col0 = wn * 64;
    const int bm = blockIdx.y * BM, bn = blockIdx.x * BN;

    // ---- loader mapping
    // A: thread t -> row t>>1, 16 floats at (t&1)*16  (4 x 16B)
    // B: thread t -> row t, 32 floats                 (8 x 16B)
    const int larow = tid >> 1;
    const int lacol = (tid & 1) * 16;
    int arow = bm + larow; if (arow >= M) arow = M - 1;
    const float* rpa[3];
    rpa[0] = seg_row_ptr(A, 0, arow);
    rpa[1] = (K > 512)  ? seg_row_ptr(A, 1, arow) : rpa[0];
    rpa[2] = (K > 1024) ? seg_row_ptr(A, 2, arow) : rpa[0];
    const float* bprow = Wt + (size_t)(bn + tid) * K;

    uint32_t aU[NSTG], bU[NSTG];
    #pragma unroll
    for (int s = 0; s < NSTG; s++) {
        aU[s] = smem_u32(smem + s * STAGE)         + (uint32_t)(larow * SSTRIDE + lacol) * 4;
        bU[s] = smem_u32(smem + s * STAGE + ATILE) + (uint32_t)(tid * SSTRIDE) * 4;
    }

    auto load_tile = [&](int kt, int slot) {
        const int seg = kt >> 9, kin = kt & 511;
        const float* ap = rpa[seg] + kin + lacol;
        #pragma unroll
        for (int j = 0; j < 4; j++) cpasync16(aU[slot] + j * 16, ap + j * 4);
        const float* bp = bprow + kt;
        #pragma unroll
        for (int j = 0; j < 8; j++) cpasync16(bU[slot] + j * 16, bp + j * 4);
        asm volatile("cp.async.commit_group;");
    };

    float acc[4][8][4];
    #pragma unroll
    for (int i = 0; i < 4; i++)
        #pragma unroll
        for (int j = 0; j < 8; j++)
            #pragma unroll
            for (int e = 0; e < 4; e++) acc[i][j][e] = 0.0f;

    const int T = K >> 5;
    load_tile(0, 0);
    if (T > 1) load_tile(32, 1);

    int slot = 0;
    for (int t = 0; t < T; ++t) {
        asm volatile("cp.async.wait_group 1;");
        __syncthreads();
        // refill the slot freed by iteration t-1
        if (t + 2 < T) load_tile((t + 2) << 5, (slot + 2) % NSTG);

        const float* as = smem + slot * STAGE;
        const float* ws = as + ATILE;
        #pragma unroll
        for (int kk = 0; kk < 4; kk++) {
            const int k = kk * 8;
            uint32_t af[4][4], bf[8][2];
            #pragma unroll
            for (int mt = 0; mt < 4; mt++) {
                const int r = row0 + mt * 16 + g;
                af[mt][0] = __float_as_uint(as[(r)     * SSTRIDE + k + tc]);
                af[mt][1] = __float_as_uint(as[(r + 8) * SSTRIDE + k + tc]);
                af[mt][2] = __float_as_uint(as[(r)     * SSTRIDE + k + tc + 4]);
                af[mt][3] = __float_as_uint(as[(r + 8) * SSTRIDE + k + tc + 4]);
            }
            #pragma unroll
            for (int nt = 0; nt < 8; nt++) {
                const int n = col0 + nt * 8 + g;
                bf[nt][0] = __float_as_uint(ws[n * SSTRIDE + k + tc]);
                bf[nt][1] = __float_as_uint(ws[n * SSTRIDE + k + tc + 4]);
            }
            #pragma unroll
            for (int mt = 0; mt < 4; mt++)
                #pragma unroll
                for (int nt = 0; nt < 8; nt++)
                    mma_tf32(acc[mt][nt], af[mt], bf[nt]);
        }
        slot = (slot + 1) % NSTG;
    }

    // ---- epilogue: bias + activation
    float bv[16];
    #pragma unroll
    for (int nt = 0; nt < 8; nt++) {
        bv[2 * nt]     = bias[bn + col0 + nt * 8 + 2 * tc];
        bv[2 * nt + 1] = bias[bn + col0 + nt * 8 + 2 * tc + 1];
    }
    #pragma unroll
    for (int mt = 0; mt < 4; mt++) {
        const int r0 = bm + row0 + mt * 16 + g;
        #pragma unroll
        for (int half = 0; half < 2; half++) {
            const int r = r0 + half * 8;
            if (r >= M) continue;
            float* crow = C + (size_t)r * H_DIM + bn + col0;
            #pragma unroll
            for (int nt = 0; nt < 8; nt++) {
                const int c = nt * 8 + 2 * tc;
                float x0 = acc[mt][nt][half * 2 + 0] + bv[2 * nt];
                float x1 = acc[mt][nt][half * 2 + 1] + bv[2 * nt + 1];
                float2 o;
                o.x = (ACT == 1) ? silu(x0) : x0;
                o.y = (ACT == 1) ? silu(x1) : x1;
                *(float2*)(crow + c) = o;
            }
        }
    }
}

// ---------------- weight transpose: W[K,512] -> Wt[512,K], rounded to tf32 --
__global__ void transpose_w(const float* __restrict__ in, float* __restrict__ out, int K)
{
    __shared__ float t[32][33];
    int k0 = blockIdx.x * 32, n0 = blockIdx.y * 32;
    int x = threadIdx.x, y = threadIdx.y;
    #pragma unroll
    for (int i = 0; i < 32; i += 8) {
        float v = in[(size_t)(k0 + y + i) * 512 + n0 + x];
        uint32_t rb; asm("cvt.rna.tf32.f32 %0, %1;" : "=r"(rb) : "f"(v));
        t[y + i][x] = __uint_as_float(rb);
    }
    __syncthreads();
    #pragma unroll
    for (int i = 0; i < 32; i += 8)
        out[(size_t)(n0 + y + i) * K + k0 + x] = t[x][y + i];
}

// ---------------- LayerNorm (+residual) epilogues ---------------------------
__device__ __forceinline__ void row_stats(float v0, float v1, float& mean, float& rstd)
{
    float s = v0 + v1;
    float q = v0 * v0 + v1 * v1;
    #pragma unroll
    for (int o = 16; o > 0; o >>= 1) {
        s += __shfl_xor_sync(0xffffffffu, s, o);
        q += __shfl_xor_sync(0xffffffffu, q, o);
    }
    __shared__ float ss[8], sq[8];
    int w = threadIdx.x >> 5, l = threadIdx.x & 31;
    if (l == 0) { ss[w] = s; sq[w] = q; }
    __syncthreads();
    s = ss[0] + ss[1] + ss[2] + ss[3] + ss[4] + ss[5] + ss[6] + ss[7];
    q = sq[0] + sq[1] + sq[2] + sq[3] + sq[4] + sq[5] + sq[6] + sq[7];
    mean = s * (1.0f / 512.0f);
    float var = q * (1.0f / 512.0f) - mean * mean;
    rstd = rsqrtf(var + 1e-5f);
}

__global__ void ln_res_scatter(const float* __restrict__ y, const float* __restrict__ res,
                               const float* __restrict__ g, const float* __restrict__ b,
                               const int* __restrict__ dst, float* __restrict__ agg)
{
    const int row = blockIdx.x;
    const int t = threadIdx.x;
    const float* yr = y + (size_t)row * H_DIM;
    float v0 = yr[t], v1 = yr[t + 256];
    float mean, rstd;
    row_stats(v0, v1, mean, rstd);
    const float* rr = res + (size_t)row * H_DIM;
    float o0 = (v0 - mean) * rstd * g[t]       + b[t]       + rr[t];
    float o1 = (v1 - mean) * rstd * g[t + 256] + b[t + 256] + rr[t + 256];
    float* ag = agg + (size_t)dst[row] * H_DIM;
    atomicAdd(&ag[t],       o0);
    atomicAdd(&ag[t + 256], o1);
}

__global__ void ln_res_out(const float* __restrict__ y, const float* __restrict__ res,
                           const float* __restrict__ g, const float* __restrict__ b,
                           float* __restrict__ out)
{
    const int row = blockIdx.x;
    const int t = threadIdx.x;
    const float* yr = y + (size_t)row * H_DIM;
    float v0 = yr[t], v1 = yr[t + 256];
    float mean, rstd;
    row_stats(v0, v1, mean, rstd);
    const float* rr = res + (size_t)row * H_DIM;
    float* orow = out + (size_t)row * H_DIM;
    orow[t]       = (v0 - mean) * rstd * g[t]       + b[t]       + rr[t];
    orow[t + 256] = (v1 - mean) * rstd * g[t + 256] + b[t + 256] + rr[t + 256];
}

__global__ void zero_kernel(float* __restrict__ p, int n)
{
    int i = blockIdx.x * blockDim.x + threadIdx.x;
    if (i < n) p[i] = 0.0f;
}

// ---------------------------------------------------------------------------
extern "C" void kernel_launch(void* const* d_in, const int* in_sizes, int n_in,
                              void* d_out, int out_size)
{
    const float* grid_f = (const float*)d_in[0];
    const float* mesh_f = (const float*)d_in[1];
    const float* edge_f = (const float*)d_in[2];
    const int*   src    = (const int*)d_in[3];
    const int*   dst    = (const int*)d_in[4];
    const float* We1 = (const float*)d_in[5];  const float* be1 = (const float*)d_in[6];
    const float* We2 = (const float*)d_in[7];  const float* be2 = (const float*)d_in[8];
    const float* ge  = (const float*)d_in[9];  const float* bbe = (const float*)d_in[10];
    const float* Wn1 = (const float*)d_in[11]; const float* bn1 = (const float*)d_in[12];
    const float* Wn2 = (const float*)d_in[13]; const float* bn2 = (const float*)d_in[14];
    const float* gn  = (const float*)d_in[15]; const float* bbn = (const float*)d_in[16];
    const float* Wg1 = (const float*)d_in[17]; const float* bg1 = (const float*)d_in[18];
    const float* Wg2 = (const float*)d_in[19]; const float* bg2 = (const float*)d_in[20];
    const float* gg  = (const float*)d_in[21]; const float* bbg = (const float*)d_in[22];

    float *h, *y, *agg, *wt;
    cudaGetSymbolAddress((void**)&h,   g_h);
    cudaGetSymbolAddress((void**)&y,   g_y);
    cudaGetSymbolAddress((void**)&agg, g_agg);
    cudaGetSymbolAddress((void**)&wt,  g_wt);

    cudaFuncSetAttribute(tc_gemm<0>, cudaFuncAttributeMaxDynamicSharedMemorySize, SMEM_BYTES);
    cudaFuncSetAttribute(tc_gemm<1>, cudaFuncAttributeMaxDynamicSharedMemorySize, SMEM_BYTES);

    float* grid_out = (float*)d_out;
    float* mesh_out = (float*)d_out + (size_t)NGRID * H_DIM;

    dim3 tb(32, 8);
    transpose_w<<<dim3(48, 16), tb>>>(We1, wt + OFF_WE1T, 1536);
    transpose_w<<<dim3(32, 16), tb>>>(Wn1, wt + OFF_WN1T, 1024);
    transpose_w<<<dim3(16, 16), tb>>>(We2, wt + OFF_WE2T, 512);
    transpose_w<<<dim3(16, 16), tb>>>(Wn2, wt + OFF_WN2T, 512);
    transpose_w<<<dim3(16, 16), tb>>>(Wg1, wt + OFF_WG1T, 512);
    transpose_w<<<dim3(16, 16), tb>>>(Wg2, wt + OFF_WG2T, 512);

    { int n = NMESH * H_DIM; zero_kernel<<<(n + 255) / 256, 256>>>(agg, n); }

    // --- MeshEdgeBlock
    {
        AView Ae = { edge_f, nullptr, grid_f, src, mesh_f, dst };
        tc_gemm<1><<<dim3(2, NEDGE / 128), 256, SMEM_BYTES>>>(Ae, wt + OFF_WE1T, be1, h, NEDGE, 1536);
        AView Ah = { h, nullptr, nullptr, nullptr, nullptr, nullptr };
        tc_gemm<0><<<dim3(2, NEDGE / 128), 256, SMEM_BYTES>>>(Ah, wt + OFF_WE2T, be2, y, NEDGE, 512);
        ln_res_scatter<<<NEDGE, 256>>>(y, edge_f, ge, bbe, dst, agg);
    }
    // --- MeshNodeBlock
    {
        AView An = { mesh_f, nullptr, agg, nullptr, nullptr, nullptr };
        int gy = (NMESH + BM - 1) / BM;
        tc_gemm<1><<<dim3(2, gy), 256, SMEM_BYTES>>>(An, wt + OFF_WN1T, bn1, h, NMESH, 1024);
        AView Ah = { h, nullptr, nullptr, nullptr, nullptr, nullptr };
        tc_gemm<0><<<dim3(2, gy), 256, SMEM_BYTES>>>(Ah, wt + OFF_WN2T, bn2, y, NMESH, 512);
        ln_res_out<<<NMESH, 256>>>(y, mesh_f, gn, bbn, mesh_out);
    }
    // --- Grid node MLP
    {
        AView Ag = { grid_f, nullptr, nullptr, nullptr, nullptr, nullptr };
        tc_gemm<1><<<dim3(2, NGRID / 128), 256, SMEM_BYTES>>>(Ag, wt + OFF_WG1T, bg1, h, NGRID, 512);
        AView Ah = { h, nullptr, nullptr, nullptr, nullptr, nullptr };
        tc_gemm<0><<<dim3(2, NGRID / 128), 256, SMEM_BYTES>>>(Ah, wt + OFF_WG2T, bg2, y, NGRID, 512);
        ln_res_out<<<NGRID, 256>>>(y, grid_f, gg, bbg, grid_out);
    }
}

// round 5
// speedup vs baseline: 4.3477x; 1.9164x over previous
#include <cuda_runtime.h>
#include <cuda_fp16.h>
#include <math.h>
#include <stdint.h>

#define H_DIM  512
#define NGRID  65536
#define NMESH  10242
#define NEDGE  131072

// ---------------- scratch (device globals: allocation-guard safe) ----------
__device__ __half g_e16[(size_t)NEDGE * H_DIM];   // edge feats fp16
__device__ __half g_g16[(size_t)NGRID * H_DIM];   // grid feats fp16
__device__ __half g_m16[(size_t)NMESH * H_DIM];   // mesh feats fp16
__device__ __half g_agg16[(size_t)NMESH * H_DIM]; // agg fp16
__device__ __half g_h16[(size_t)NEDGE * H_DIM];   // hidden fp16
__device__ float  g_y[(size_t)NEDGE * H_DIM];     // pre-LN output fp32
__device__ float  g_agg[(size_t)NMESH * H_DIM];   // segment-sum fp32
__device__ __half g_wt16[(size_t)512 * 4608];     // transposed weights fp16 [N, K]

#define OFF_WE1T 0
#define OFF_WN1T (512*1536)
#define OFF_WE2T (OFF_WN1T + 512*1024)
#define OFF_WN2T (OFF_WE2T + 512*512)
#define OFF_WG1T (OFF_WN2T + 512*512)
#define OFF_WG2T (OFF_WG1T + 512*512)

// Virtual concatenated fp16 A matrix: segment s covers cols [s*512,(s+1)*512)
struct AViewH {
    const __half* base0; const int* idx0;
    const __half* base1; const int* idx1;
    const __half* base2; const int* idx2;
};

__device__ __forceinline__ const __half* seg_row_ptr(const AViewH& A, int seg, int r) {
    const __half* b; const int* ix;
    if (seg == 0)      { b = A.base0; ix = A.idx0; }
    else if (seg == 1) { b = A.base1; ix = A.idx1; }
    else               { b = A.base2; ix = A.idx2; }
    int ar = ix ? ix[r] : r;
    return b + (size_t)ar * H_DIM;
}

__device__ __forceinline__ float silu(float x) { return x / (1.0f + expf(-x)); }

__device__ __forceinline__ uint32_t smem_u32(const void* p) {
    uint32_t a;
    asm("{ .reg .u64 t; cvta.to.shared.u64 t, %1; cvt.u32.u64 %0, t; }" : "=r"(a) : "l"(p));
    return a;
}
__device__ __forceinline__ void cpasync16(uint32_t s, const void* g) {
    asm volatile("cp.async.cg.shared.global [%0], [%1], 16;" :: "r"(s), "l"(g));
}
__device__ __forceinline__ void mma_f16(float* d, const uint32_t* a, const uint32_t* b) {
    asm volatile(
        "mma.sync.aligned.m16n8k16.row.col.f32.f16.f16.f32 "
        "{%0,%1,%2,%3}, {%4,%5,%6,%7}, {%8,%9}, {%0,%1,%2,%3};"
        : "+f"(d[0]), "+f"(d[1]), "+f"(d[2]), "+f"(d[3])
        : "r"(a[0]), "r"(a[1]), "r"(a[2]), "r"(a[3]), "r"(b[0]), "r"(b[1]));
}

// ---------------- fp16 tensor-core GEMM: C = act(A @ Wt^T + bias) -----------
// BM=128, BN=256, BK=32(halfs). 512 threads = 16 warps (4m x 4n), warp 32x64.
// Smem: row = 32 halfs = 16 words, padded to SW=20 words -> conflict-free
// (bank(g) = 20g % 32 = {0,20,8,28,16,4,24,12}, +tc in 0..3, all distinct).
#define BM 128
#define BN 256
#define SW  20
#define ATW (128 * SW)
#define BTW (256 * SW)
#define STW (ATW + BTW)
#define NSTG 3
#define SMEM_BYTES (NSTG * STW * 4)

template<int ACT, int OUT_HALF>
__global__ __launch_bounds__(512)
void tc_gemm(AViewH A, const __half* __restrict__ Wt, const float* __restrict__ bias,
             void* __restrict__ Cv, int M, int K)
{
    extern __shared__ uint32_t smw[];

    const int tid = threadIdx.x, wid = tid >> 5, lane = tid & 31;
    const int g = lane >> 2, tc = lane & 3;
    const int wm = wid & 3, wn = wid >> 2;               // 4 x 4 warp grid
    const int row0 = wm * 32, col0 = wn * 64;
    const int bm = blockIdx.y * BM, bn = blockIdx.x * BN;

    // ---- loader mapping: 16B chunks. A: 512 chunks (one/thread). B: 1024 (two/thread).
    const int lr = tid >> 2;          // 0..127
    const int lc = tid & 3;           // chunk within row (8 halfs each)
    int arow = bm + lr; if (arow >= M) arow = M - 1;
    const __half* rpa[3];
    rpa[0] = seg_row_ptr(A, 0, arow);
    rpa[1] = (K > 512)  ? seg_row_ptr(A, 1, arow) : rpa[0];
    rpa[2] = (K > 1024) ? seg_row_ptr(A, 2, arow) : rpa[0];
    const __half* bp0 = Wt + (size_t)(bn + lr) * K;
    const __half* bp1 = Wt + (size_t)(bn + lr + 128) * K;

    const uint32_t sbase = smem_u32(smw);
    const uint32_t aOff  = ((uint32_t)(lr * SW + lc * 4)) * 4;
    const uint32_t bOff0 = ((uint32_t)(lr * SW + lc * 4)) * 4;
    const uint32_t bOff1 = ((uint32_t)((lr + 128) * SW + lc * 4)) * 4;

    auto load_tile = [&](int kt, int slot) {
        const int seg = kt >> 9, kin = kt & 511;
        const uint32_t sA = sbase + (uint32_t)(slot * STW) * 4;
        const uint32_t sB = sA + (uint32_t)ATW * 4;
        cpasync16(sA + aOff,  rpa[seg] + kin + lc * 8);
        cpasync16(sB + bOff0, bp0 + kt + lc * 8);
        cpasync16(sB + bOff1, bp1 + kt + lc * 8);
        asm volatile("cp.async.commit_group;");
    };

    float acc[2][8][4];
    #pragma unroll
    for (int i = 0; i < 2; i++)
        #pragma unroll
        for (int j = 0; j < 8; j++)
            #pragma unroll
            for (int e = 0; e < 4; e++) acc[i][j][e] = 0.0f;

    const int T = K >> 5;
    load_tile(0, 0);
    if (T > 1) load_tile(32, 1);

    int slot = 0;
    for (int t = 0; t < T; ++t) {
        asm volatile("cp.async.wait_group 1;");
        __syncthreads();
        if (t + 2 < T) load_tile((t + 2) << 5, (slot + 2) % NSTG);

        const uint32_t* as = smw + slot * STW;
        const uint32_t* ws = as + ATW;
        #pragma unroll
        for (int kk = 0; kk < 2; kk++) {
            const int k0 = kk * 8;     // word offset of this k16 step
            uint32_t af[2][4], bf[8][2];
            #pragma unroll
            for (int mt = 0; mt < 2; mt++) {
                const int r = row0 + mt * 16 + g;
                const int b0 = r * SW + k0 + tc;
                af[mt][0] = as[b0];
                af[mt][1] = as[b0 + 8 * SW];
                af[mt][2] = as[b0 + 4];
                af[mt][3] = as[b0 + 8 * SW + 4];
            }
            #pragma unroll
            for (int nt = 0; nt < 8; nt++) {
                const int n = col0 + nt * 8 + g;
                const int b0 = n * SW + k0 + tc;
                bf[nt][0] = ws[b0];
                bf[nt][1] = ws[b0 + 4];
            }
            #pragma unroll
            for (int mt = 0; mt < 2; mt++)
                #pragma unroll
                for (int nt = 0; nt < 8; nt++)
                    mma_f16(acc[mt][nt], af[mt], bf[nt]);
        }
        slot = (slot + 1) % NSTG;
    }

    // ---- epilogue: bias + activation
    float bv[16];
    #pragma unroll
    for (int nt = 0; nt < 8; nt++) {
        bv[2 * nt]     = bias[bn + col0 + nt * 8 + 2 * tc];
        bv[2 * nt + 1] = bias[bn + col0 + nt * 8 + 2 * tc + 1];
    }
    #pragma unroll
    for (int mt = 0; mt < 2; mt++) {
        const int r0 = bm + row0 + mt * 16 + g;
        #pragma unroll
        for (int half = 0; half < 2; half++) {
            const int r = r0 + half * 8;
            if (r >= M) continue;
            #pragma unroll
            for (int nt = 0; nt < 8; nt++) {
                const int c = nt * 8 + 2 * tc;
                float x0 = acc[mt][nt][half * 2 + 0] + bv[2 * nt];
                float x1 = acc[mt][nt][half * 2 + 1] + bv[2 * nt + 1];
                if (ACT == 1) { x0 = silu(x0); x1 = silu(x1); }
                if (OUT_HALF) {
                    __half2* Ch = (__half2*)((__half*)Cv + (size_t)r * H_DIM + bn + col0 + c);
                    *Ch = __floats2half2_rn(x0, x1);
                } else {
                    float2 o; o.x = x0; o.y = x1;
                    *(float2*)((float*)Cv + (size_t)r * H_DIM + bn + col0 + c) = o;
                }
            }
        }
    }
}

// ---------------- weight transpose: W[K,512] fp32 -> Wt[512,K] fp16 ---------
__global__ void transpose_w16(const float* __restrict__ in, __half* __restrict__ out, int K)
{
    __shared__ float t[32][33];
    int k0 = blockIdx.x * 32, n0 = blockIdx.y * 32;
    int x = threadIdx.x, y = threadIdx.y;
    #pragma unroll
    for (int i = 0; i < 32; i += 8)
        t[y + i][x] = in[(size_t)(k0 + y + i) * 512 + n0 + x];
    __syncthreads();
    #pragma unroll
    for (int i = 0; i < 32; i += 8)
        out[(size_t)(n0 + y + i) * K + k0 + x] = __float2half_rn(t[x][y + i]);
}

// ---------------- fp32 -> fp16 bulk convert ---------------------------------
__global__ void f32_to_f16(const float* __restrict__ in, __half* __restrict__ out, size_t n)
{
    size_t i = ((size_t)blockIdx.x * blockDim.x + threadIdx.x) * 8;
    if (i >= n) return;
    float4 v0 = *(const float4*)(in + i);
    float4 v1 = *(const float4*)(in + i + 4);
    __half2 h[4];
    h[0] = __floats2half2_rn(v0.x, v0.y);
    h[1] = __floats2half2_rn(v0.z, v0.w);
    h[2] = __floats2half2_rn(v1.x, v1.y);
    h[3] = __floats2half2_rn(v1.z, v1.w);
    *(uint4*)(out + i) = *(uint4*)h;
}

// ---------------- LayerNorm (+residual) epilogues ---------------------------
__device__ __forceinline__ void row_stats(float v0, float v1, float& mean, float& rstd)
{
    float s = v0 + v1;
    float q = v0 * v0 + v1 * v1;
    #pragma unroll
    for (int o = 16; o > 0; o >>= 1) {
        s += __shfl_xor_sync(0xffffffffu, s, o);
        q += __shfl_xor_sync(0xffffffffu, q, o);
    }
    __shared__ float ss[8], sq[8];
    int w = threadIdx.x >> 5, l = threadIdx.x & 31;
    if (l == 0) { ss[w] = s; sq[w] = q; }
    __syncthreads();
    s = ss[0] + ss[1] + ss[2] + ss[3] + ss[4] + ss[5] + ss[6] + ss[7];
    q = sq[0] + sq[1] + sq[2] + sq[3] + sq[4] + sq[5] + sq[6] + sq[7];
    mean = s * (1.0f / 512.0f);
    float var = q * (1.0f / 512.0f) - mean * mean;
    rstd = rsqrtf(var + 1e-5f);
}

__global__ void ln_res_scatter(const float* __restrict__ y, const float* __restrict__ res,
                               const float* __restrict__ g, const float* __restrict__ b,
                               const int* __restrict__ dst, float* __restrict__ agg)
{
    const int row = blockIdx.x;
    const int t = threadIdx.x;
    const float* yr = y + (size_t)row * H_DIM;
    float v0 = yr[t], v1 = yr[t + 256];
    float mean, rstd;
    row_stats(v0, v1, mean, rstd);
    const float* rr = res + (size_t)row * H_DIM;
    float o0 = (v0 - mean) * rstd * g[t]       + b[t]       + rr[t];
    float o1 = (v1 - mean) * rstd * g[t + 256] + b[t + 256] + rr[t + 256];
    float* ag = agg + (size_t)dst[row] * H_DIM;
    atomicAdd(&ag[t],       o0);
    atomicAdd(&ag[t + 256], o1);
}

__global__ void ln_res_out(const float* __restrict__ y, const float* __restrict__ res,
                           const float* __restrict__ g, const float* __restrict__ b,
                           float* __restrict__ out)
{
    const int row = blockIdx.x;
    const int t = threadIdx.x;
    const float* yr = y + (size_t)row * H_DIM;
    float v0 = yr[t], v1 = yr[t + 256];
    float mean, rstd;
    row_stats(v0, v1, mean, rstd);
    const float* rr = res + (size_t)row * H_DIM;
    float* orow = out + (size_t)row * H_DIM;
    orow[t]       = (v0 - mean) * rstd * g[t]       + b[t]       + rr[t];
    orow[t + 256] = (v1 - mean) * rstd * g[t + 256] + b[t + 256] + rr[t + 256];
}

__global__ void zero_kernel(float* __restrict__ p, int n)
{
    int i = blockIdx.x * blockDim.x + threadIdx.x;
    if (i < n) p[i] = 0.0f;
}

// ---------------------------------------------------------------------------
extern "C" void kernel_launch(void* const* d_in, const int* in_sizes, int n_in,
                              void* d_out, int out_size)
{
    const float* grid_f = (const float*)d_in[0];
    const float* mesh_f = (const float*)d_in[1];
    const float* edge_f = (const float*)d_in[2];
    const int*   src    = (const int*)d_in[3];
    const int*   dst    = (const int*)d_in[4];
    const float* We1 = (const float*)d_in[5];  const float* be1 = (const float*)d_in[6];
    const float* We2 = (const float*)d_in[7];  const float* be2 = (const float*)d_in[8];
    const float* ge  = (const float*)d_in[9];  const float* bbe = (const float*)d_in[10];
    const float* Wn1 = (const float*)d_in[11]; const float* bn1 = (const float*)d_in[12];
    const float* Wn2 = (const float*)d_in[13]; const float* bn2 = (const float*)d_in[14];
    const float* gn  = (const float*)d_in[15]; const float* bbn = (const float*)d_in[16];
    const float* Wg1 = (const float*)d_in[17]; const float* bg1 = (const float*)d_in[18];
    const float* Wg2 = (const float*)d_in[19]; const float* bg2 = (const float*)d_in[20];
    const float* gg  = (const float*)d_in[21]; const float* bbg = (const float*)d_in[22];

    __half *e16, *g16, *m16, *agg16, *h16, *wt;
    float *y, *agg;
    cudaGetSymbolAddress((void**)&e16,   g_e16);
    cudaGetSymbolAddress((void**)&g16,   g_g16);
    cudaGetSymbolAddress((void**)&m16,   g_m16);
    cudaGetSymbolAddress((void**)&agg16, g_agg16);
    cudaGetSymbolAddress((void**)&h16,   g_h16);
    cudaGetSymbolAddress((void**)&y,     g_y);
    cudaGetSymbolAddress((void**)&agg,   g_agg);
    cudaGetSymbolAddress((void**)&wt,    g_wt16);

    cudaFuncSetAttribute(tc_gemm<0,0>, cudaFuncAttributeMaxDynamicSharedMemorySize, SMEM_BYTES);
    cudaFuncSetAttribute(tc_gemm<1,1>, cudaFuncAttributeMaxDynamicSharedMemorySize, SMEM_BYTES);

    float* grid_out = (float*)d_out;
    float* mesh_out = (float*)d_out + (size_t)NGRID * H_DIM;

    dim3 tb(32, 8);
    transpose_w16<<<dim3(48, 16), tb>>>(We1, wt + OFF_WE1T, 1536);
    transpose_w16<<<dim3(32, 16), tb>>>(Wn1, wt + OFF_WN1T, 1024);
    transpose_w16<<<dim3(16, 16), tb>>>(We2, wt + OFF_WE2T, 512);
    transpose_w16<<<dim3(16, 16), tb>>>(Wn2, wt + OFF_WN2T, 512);
    transpose_w16<<<dim3(16, 16), tb>>>(Wg1, wt + OFF_WG1T, 512);
    transpose_w16<<<dim3(16, 16), tb>>>(Wg2, wt + OFF_WG2T, 512);

    // fp16 activation copies
    {
        size_t ne = (size_t)NEDGE * H_DIM, ng = (size_t)NGRID * H_DIM, nm = (size_t)NMESH * H_DIM;
        f32_to_f16<<<(unsigned)((ne / 8 + 255) / 256), 256>>>(edge_f, e16, ne);
        f32_to_f16<<<(unsigned)((ng / 8 + 255) / 256), 256>>>(grid_f, g16, ng);
        f32_to_f16<<<(unsigned)((nm / 8 + 255) / 256), 256>>>(mesh_f, m16, nm);
    }
    { int n = NMESH * H_DIM; zero_kernel<<<(n + 255) / 256, 256>>>(agg, n); }

    // --- MeshEdgeBlock
    {
        AViewH Ae = { e16, nullptr, g16, src, m16, dst };
        tc_gemm<1,1><<<dim3(2, NEDGE / 128), 512, SMEM_BYTES>>>(Ae, wt + OFF_WE1T, be1, h16, NEDGE, 1536);
        AViewH Ah = { h16, nullptr, nullptr, nullptr, nullptr, nullptr };
        tc_gemm<0,0><<<dim3(2, NEDGE / 128), 512, SMEM_BYTES>>>(Ah, wt + OFF_WE2T, be2, y, NEDGE, 512);
        ln_res_scatter<<<NEDGE, 256>>>(y, edge_f, ge, bbe, dst, agg);
    }
    // --- MeshNodeBlock
    {
        size_t nm = (size_t)NMESH * H_DIM;
        f32_to_f16<<<(unsigned)((nm / 8 + 255) / 256), 256>>>(agg, agg16, nm);
        AViewH An = { m16, nullptr, agg16, nullptr, nullptr, nullptr };
        int gy = (NMESH + BM - 1) / BM;
        tc_gemm<1,1><<<dim3(2, gy), 512, SMEM_BYTES>>>(An, wt + OFF_WN1T, bn1, h16, NMESH, 1024);
        AViewH Ah = { h16, nullptr, nullptr, nullptr, nullptr, nullptr };
        tc_gemm<0,0><<<dim3(2, gy), 512, SMEM_BYTES>>>(Ah, wt + OFF_WN2T, bn2, y, NMESH, 512);
        ln_res_out<<<NMESH, 256>>>(y, mesh_f, gn, bbn, mesh_out);
    }
    // --- Grid node MLP
    {
        AViewH Ag = { g16, nullptr, nullptr, nullptr, nullptr, nullptr };
        tc_gemm<1,1><<<dim3(2, NGRID / 128), 512, SMEM_BYTES>>>(Ag, wt + OFF_WG1T, bg1, h16, NGRID, 512);
        AViewH Ah = { h16, nullptr, nullptr, nullptr, nullptr, nullptr };
        tc_gemm<0,0><<<dim3(2, NGRID / 128), 512, SMEM_BYTES>>>(Ah, wt + OFF_WG2T, bg2, y, NGRID, 512);
        ln_res_out<<<NGRID, 256>>>(y, grid_f, gg, bbg, grid_out);
    }
}